// round 4
// baseline (speedup 1.0000x reference)
#include <cuda_runtime.h>

// ChannelPruner: out[b,o,h,w] = sum_c W[o,c] * x[b,c,h,w]
// Kernel 1: one warp per W row, ballot+popc compaction into device scratch (~1-2us).
// Kernel 2: pure streaming sparse-dot, no divisions, no barriers, default cache ops
// (L2 reuse across graph replays is real: measured traffic < cold-HBM model).
// R3 was an infra flake (device busy at harness init) — same theory, rebenched,
// plus tail-block trim: grid.x=3, thread p<16 also handles p+768.

#define N_CH   256
#define HW4    784               // 56*56/4 float4 per channel-plane
#define BATCH  32

__device__ int   g_nnz[N_CH];
__device__ int   g_col[N_CH * N_CH];
__device__ float g_val[N_CH * N_CH];

// --- Kernel 1: warp-per-row compaction (32 blocks x 8 warps = 256 warps) ---
__global__ void __launch_bounds__(256)
compact_rows_kernel(const float* __restrict__ w) {
    const int warp = threadIdx.x >> 5;
    const int lane = threadIdx.x & 31;
    const int o    = blockIdx.x * 8 + warp;      // 0..255

    const float* row = w + o * N_CH;
    int*   cols = g_col + o * N_CH;
    float* vals = g_val + o * N_CH;

    int off = 0;
    #pragma unroll
    for (int ch = 0; ch < N_CH / 32; ++ch) {
        float v = row[ch * 32 + lane];
        unsigned m = __ballot_sync(0xffffffffu, v != 0.0f);
        int pre = __popc(m & ((1u << lane) - 1u));
        if (v != 0.0f) {
            cols[off + pre] = ch * 32 + lane;
            vals[off + pre] = v;
        }
        off += __popc(m);
    }
    if (lane == 0) g_nnz[o] = off;
}

// --- Kernel 2: streaming sparse-dot, grid(3, 256, 32), block 256 ---
// p = blockIdx.x*256 + tid; threads with p < 16 also handle p + 768.
__global__ void __launch_bounds__(256)
prune_stream_kernel(const float* __restrict__ x, float* __restrict__ out) {
    const int p = blockIdx.x * 256 + threadIdx.x;   // 0..767
    const int o = blockIdx.y;
    const int b = blockIdx.z;

    const int n = g_nnz[o];

    const int*   cols = g_col + o * N_CH;
    const float* vals = g_val + o * N_CH;

    const float4* xb = (const float4*)x + (b * N_CH) * HW4;
    float4*       ob = (float4*)out + (b * N_CH + o) * HW4;

    float4 acc = make_float4(0.f, 0.f, 0.f, 0.f);
    for (int j = 0; j < n; ++j) {
        float  v  = vals[j];
        float4 xv = xb[cols[j] * HW4 + p];
        acc.x = fmaf(v, xv.x, acc.x);
        acc.y = fmaf(v, xv.y, acc.y);
        acc.z = fmaf(v, xv.z, acc.z);
        acc.w = fmaf(v, xv.w, acc.w);
    }
    ob[p] = acc;

    if (p < HW4 - 768) {                            // p < 16: tail element
        const int pt = p + 768;
        float4 acc2 = make_float4(0.f, 0.f, 0.f, 0.f);
        for (int j = 0; j < n; ++j) {
            float  v  = vals[j];
            float4 xv = xb[cols[j] * HW4 + pt];
            acc2.x = fmaf(v, xv.x, acc2.x);
            acc2.y = fmaf(v, xv.y, acc2.y);
            acc2.z = fmaf(v, xv.z, acc2.z);
            acc2.w = fmaf(v, xv.w, acc2.w);
        }
        ob[pt] = acc2;
    }
}

extern "C" void kernel_launch(void* const* d_in, const int* in_sizes, int n_in,
                              void* d_out, int out_size) {
    const float* x = (const float*)d_in[0];   // (32,256,56,56) fp32
    const float* w = (const float*)d_in[1];   // (256,256,1,1)  fp32
    float* out = (float*)d_out;

    compact_rows_kernel<<<32, 256>>>(w);

    dim3 grid(3, N_CH, BATCH);                // 768 float4 + 16 tail, per (o,b)
    prune_stream_kernel<<<grid, 256>>>(x, out);
}

// round 5
// speedup vs baseline: 1.1240x; 1.1240x over previous
#include <cuda_runtime.h>

// ChannelPruner: out[b,o,h,w] = sum_c W[o,c] * x[b,c,h,w]
// Composition of the two best measured pieces:
//  - Kernel 1: warp-per-row ballot+popc compaction (~2us measured).
//  - Kernel 2: R1's flat one-thread-one-float4 stream (30.1us, DRAM 54%
//    measured) with int32 indexing only (div/mod by 784 -> umulhi magic).
// No cache hints, no tail special-casing, no per-plane grids — each of those
// was tried and measured slower (R2: 33.5, R4: 36.2).

#define N_CH   256
#define HW4    784               // 56*56/4 float4 per channel-plane
#define BATCH  32
#define TOTAL4 (BATCH * N_CH * HW4)   // 6,422,528 float4 (< 2^31)

__device__ int   g_nnz[N_CH];
__device__ int   g_col[N_CH * N_CH];
__device__ float g_val[N_CH * N_CH];

// --- Kernel 1: warp-per-row compaction (32 blocks x 8 warps = 256 warps) ---
__global__ void __launch_bounds__(256)
compact_rows_kernel(const float* __restrict__ w) {
    const int warp = threadIdx.x >> 5;
    const int lane = threadIdx.x & 31;
    const int o    = blockIdx.x * 8 + warp;      // 0..255

    const float* row = w + o * N_CH;
    int*   cols = g_col + o * N_CH;
    float* vals = g_val + o * N_CH;

    int off = 0;
    #pragma unroll
    for (int ch = 0; ch < N_CH / 32; ++ch) {
        float v = row[ch * 32 + lane];
        unsigned m = __ballot_sync(0xffffffffu, v != 0.0f);
        int pre = __popc(m & ((1u << lane) - 1u));
        if (v != 0.0f) {
            cols[off + pre] = ch * 32 + lane;
            vals[off + pre] = v;
        }
        off += __popc(m);
    }
    if (lane == 0) g_nnz[o] = off;
}

// --- Kernel 2: flat streaming sparse-dot, one thread per output float4 ---
__global__ void __launch_bounds__(256)
prune_stream_kernel(const float* __restrict__ x, float* __restrict__ out) {
    const int idx = blockIdx.x * 256 + threadIdx.x;     // 0..TOTAL4-1, int32

    const int p4 = idx % HW4;        // umulhi magic-number division
    const int bo = idx / HW4;        // b*256 + o
    const int o  = bo & (N_CH - 1);
    const int b  = bo >> 8;

    const int n = g_nnz[o];
    float4 acc = make_float4(0.f, 0.f, 0.f, 0.f);

    const float4* xb   = (const float4*)x + b * (N_CH * HW4) + p4;
    const int*    cols = g_col + o * N_CH;
    const float*  vals = g_val + o * N_CH;

    for (int j = 0; j < n; ++j) {
        float  v  = vals[j];
        float4 xv = xb[cols[j] * HW4];
        acc.x = fmaf(v, xv.x, acc.x);
        acc.y = fmaf(v, xv.y, acc.y);
        acc.z = fmaf(v, xv.z, acc.z);
        acc.w = fmaf(v, xv.w, acc.w);
    }

    ((float4*)out)[idx] = acc;
}

extern "C" void kernel_launch(void* const* d_in, const int* in_sizes, int n_in,
                              void* d_out, int out_size) {
    const float* x = (const float*)d_in[0];   // (32,256,56,56) fp32
    const float* w = (const float*)d_in[1];   // (256,256,1,1)  fp32
    float* out = (float*)d_out;

    compact_rows_kernel<<<32, 256>>>(w);

    prune_stream_kernel<<<TOTAL4 / 256, 256>>>(x, out);   // 25088 blocks
}

// round 6
// speedup vs baseline: 1.1760x; 1.0463x over previous
#include <cuda_runtime.h>

// ChannelPruner: out[b,o,h,w] = sum_c W[o,c] * x[b,c,h,w]
//  - Kernel 1: warp-per-row ballot+popc compaction (~2us measured).
//  - Kernel 2: flat streaming sparse-dot with ILP=2: each thread computes two
//    output float4 at p4 and p4+392 within the SAME (b,o) plane. Independent
//    x-loads double MLP; the div/mod + metadata chain is amortized over both.
// Measured history: flat 1-elt/thread = 29.5us @ DRAM 55%; this targets the
// MLP_p1=1 limit (B300: spread/bandwidth scales with front-batched loads).

#define N_CH   256
#define HW4    784               // 56*56/4 float4 per channel-plane
#define HALF4  392
#define BATCH  32
#define TOTAL4 (BATCH * N_CH * HW4)    // 6,422,528 float4
#define NTHREAD (TOTAL4 / 2)           // 3,211,264 threads, one per 2 outputs

__device__ int   g_nnz[N_CH];
__device__ int   g_col[N_CH * N_CH];
__device__ float g_val[N_CH * N_CH];

// --- Kernel 1: warp-per-row compaction (32 blocks x 8 warps = 256 warps) ---
__global__ void __launch_bounds__(256)
compact_rows_kernel(const float* __restrict__ w) {
    const int warp = threadIdx.x >> 5;
    const int lane = threadIdx.x & 31;
    const int o    = blockIdx.x * 8 + warp;      // 0..255

    const float* row = w + o * N_CH;
    int*   cols = g_col + o * N_CH;
    float* vals = g_val + o * N_CH;

    int off = 0;
    #pragma unroll
    for (int ch = 0; ch < N_CH / 32; ++ch) {
        float v = row[ch * 32 + lane];
        unsigned m = __ballot_sync(0xffffffffu, v != 0.0f);
        int pre = __popc(m & ((1u << lane) - 1u));
        if (v != 0.0f) {
            cols[off + pre] = ch * 32 + lane;
            vals[off + pre] = v;
        }
        off += __popc(m);
    }
    if (lane == 0) g_nnz[o] = off;
}

// --- Kernel 2: streaming sparse-dot, 2 float4 per thread (same plane) ---
__global__ void __launch_bounds__(256)
prune_stream_kernel(const float* __restrict__ x, float* __restrict__ out) {
    const int idx = blockIdx.x * 256 + threadIdx.x;   // 0..NTHREAD-1

    const int p4 = idx % HALF4;       // 0..391 (umulhi magic division)
    const int bo = idx / HALF4;       // b*256 + o
    const int o  = bo & (N_CH - 1);
    const int b  = bo >> 8;

    const int n = g_nnz[o];

    const float4* xb   = (const float4*)x + b * (N_CH * HW4) + p4;
    const int*    cols = g_col + o * N_CH;
    const float*  vals = g_val + o * N_CH;

    float4 acc0 = make_float4(0.f, 0.f, 0.f, 0.f);
    float4 acc1 = acc0;

    for (int j = 0; j < n; ++j) {
        float v = vals[j];
        const float4* xc = xb + cols[j] * HW4;
        float4 xv0 = xc[0];           // independent loads -> MLP 2
        float4 xv1 = xc[HALF4];
        acc0.x = fmaf(v, xv0.x, acc0.x);
        acc0.y = fmaf(v, xv0.y, acc0.y);
        acc0.z = fmaf(v, xv0.z, acc0.z);
        acc0.w = fmaf(v, xv0.w, acc0.w);
        acc1.x = fmaf(v, xv1.x, acc1.x);
        acc1.y = fmaf(v, xv1.y, acc1.y);
        acc1.z = fmaf(v, xv1.z, acc1.z);
        acc1.w = fmaf(v, xv1.w, acc1.w);
    }

    float4* ob = (float4*)out + bo * HW4 + p4;
    ob[0]     = acc0;
    ob[HALF4] = acc1;
}

extern "C" void kernel_launch(void* const* d_in, const int* in_sizes, int n_in,
                              void* d_out, int out_size) {
    const float* x = (const float*)d_in[0];   // (32,256,56,56) fp32
    const float* w = (const float*)d_in[1];   // (256,256,1,1)  fp32
    float* out = (float*)d_out;

    compact_rows_kernel<<<32, 256>>>(w);

    prune_stream_kernel<<<NTHREAD / 256, 256>>>(x, out);   // 12544 blocks
}